// round 15
// baseline (speedup 1.0000x reference)
#include <cuda_runtime.h>
#include <cstdint>

// Problem constants (shape-fixed dataset): N=500000, C=10, V=100000, F=200000
#define MAXF 200000
#define CAND 10

// Packed per-face record (48B): [v0|un.x] [v1|un.y] [v2|un.z]
// un = fN / max(||fN||, 1e-9) precomputed with reference-identical ops.
__device__ float4 g_fv[3 * MAXF];

// ---- exact IEEE fp32 helpers (no FMA contraction, match XLA rounding) ----
__device__ __forceinline__ float fmulr(float a, float b) { return __fmul_rn(a, b); }
__device__ __forceinline__ float faddr(float a, float b) { return __fadd_rn(a, b); }
__device__ __forceinline__ float fsubr(float a, float b) { return __fsub_rn(a, b); }

struct V3 { float x, y, z; };

__device__ __forceinline__ V3 sub3(V3 a, V3 b) {
    V3 r; r.x = fsubr(a.x, b.x); r.y = fsubr(a.y, b.y); r.z = fsubr(a.z, b.z); return r;
}
// sum(a*b) left-associated: ((x+y)+z), matching jnp.sum over axis -1
__device__ __forceinline__ float dot3(V3 a, V3 b) {
    return faddr(faddr(fmulr(a.x, b.x), fmulr(a.y, b.y)), fmulr(a.z, b.z));
}
// jnp.cross: (ay*bz - az*by, az*bx - ax*bz, ax*by - ay*bx)
__device__ __forceinline__ V3 cross3(V3 a, V3 b) {
    V3 r;
    r.x = fsubr(fmulr(a.y, b.z), fmulr(a.z, b.y));
    r.y = fsubr(fmulr(a.z, b.x), fmulr(a.x, b.z));
    r.z = fsubr(fmulr(a.x, b.y), fmulr(a.y, b.x));
    return r;
}
__device__ __forceinline__ V3 sel3(bool p, V3 a, V3 b) {
    V3 r; r.x = p ? a.x : b.x; r.y = p ? a.y : b.y; r.z = p ? a.z : b.z; return r;
}

__global__ void pack_faces_kernel(const float* __restrict__ verts,
                                  const int* __restrict__ faces, int F) {
    int f = blockIdx.x * blockDim.x + threadIdx.x;
    if (f >= F) return;
    int i0 = __ldg(faces + 3 * f + 0);
    int i1 = __ldg(faces + 3 * f + 1);
    int i2 = __ldg(faces + 3 * f + 2);
    V3 v0; v0.x = __ldg(verts + 3 * i0); v0.y = __ldg(verts + 3 * i0 + 1); v0.z = __ldg(verts + 3 * i0 + 2);
    V3 v1; v1.x = __ldg(verts + 3 * i1); v1.y = __ldg(verts + 3 * i1 + 1); v1.z = __ldg(verts + 3 * i1 + 2);
    V3 v2; v2.x = __ldg(verts + 3 * i2); v2.y = __ldg(verts + 3 * i2 + 1); v2.z = __ldg(verts + 3 * i2 + 2);

    // Reference-identical unit normal computation
    V3 e10 = sub3(v1, v0);
    V3 e02 = sub3(v0, v2);
    V3 cr  = cross3(e10, e02);
    V3 fN; fN.x = -cr.x; fN.y = -cr.y; fN.z = -cr.z;
    float nn  = dot3(fN, fN);
    float nrm = __fsqrt_rn(nn);
    float den = fmaxf(nrm, 1e-9f);
    float unx = __fdiv_rn(fN.x, den);
    float uny = __fdiv_rn(fN.y, den);
    float unz = __fdiv_rn(fN.z, den);

    g_fv[3 * f + 0] = make_float4(v0.x, v0.y, v0.z, unx);
    g_fv[3 * f + 1] = make_float4(v1.x, v1.y, v1.z, uny);
    g_fv[3 * f + 2] = make_float4(v2.x, v2.y, v2.z, unz);
}

// Compute merged distance for one candidate from its already-loaded record.
__device__ __forceinline__ float cand_merged(
    V3 Q, float4 A, float4 B, float4 Cc)
{
    V3 v0; v0.x = A.x;  v0.y = A.y;  v0.z = A.z;
    V3 v1; v1.x = B.x;  v1.y = B.y;  v1.z = B.z;
    V3 v2; v2.x = Cc.x; v2.y = Cc.y; v2.z = Cc.z;
    V3 un; un.x = A.w;  un.y = B.w;  un.z = Cc.w;

    V3 e10 = sub3(v1, v0);
    V3 e21 = sub3(v2, v1);
    V3 e02 = sub3(v0, v2);

    V3 qm0 = sub3(Q, v0);
    V3 qm1 = sub3(Q, v1);
    V3 qm2 = sub3(Q, v2);

    float uab = __fdiv_rn(dot3(qm0, e10), fmaxf(dot3(e10, e10), 1e-9f));
    float ubc = __fdiv_rn(dot3(qm1, e21), fmaxf(dot3(e21, e21), 1e-9f));
    float uca = __fdiv_rn(dot3(qm2, e02), fmaxf(dot3(e02, e02), 1e-9f));

    bool t1 = (uca > 1.0f) && (uab < 0.0f);
    bool t2 = (uab > 1.0f) && (ubc < 0.0f);
    bool t3 = (ubc > 1.0f) && (uca < 0.0f);

    // fN = -cross(e10, e02) (needed only for the not-above tests)
    V3 cr = cross3(e10, e02);
    V3 fN; fN.x = -cr.x; fN.y = -cr.y; fN.z = -cr.z;
    bool na4 = dot3(cross3(fN, e10), qm0) <= 0.0f;
    bool na5 = dot3(cross3(fN, e21), qm1) <= 0.0f;
    bool na6 = dot3(cross3(fN, e02), qm2) <= 0.0f;

    bool t4 = (uab >= 0.0f) && (uab <= 1.0f) && na4;
    bool t5 = (ubc >= 0.0f) && (ubc <= 1.0f) && na5 && !t4;
    bool t6 = (uca >= 0.0f) && (uca <= 1.0f) && na6 && !t4 && !t5;
    bool t0 = !(t1 || t2 || t3 || t4 || t5 || t6);

    // Group A term: t0->d0, t1->|q-v0|, t2->|q-v1|, t3->|q-v2|  (mutually exclusive)
    float d0 = dot3(qm0, un);                       // un precomputed, bit-identical
    V3 qsel = sel3(t1, qm0, sel3(t2, qm1, qm2));    // t3 (or unused) -> qm2
    float dA = __fsqrt_rn(dot3(qsel, qsel));        // == ref d1/d2/d3 when selected
    float selA = t0 ? d0 : ((t1 || t2 || t3) ? dA : 0.0f);

    // Group B term: t4/t5/t6 (mutually exclusive) -> dist to edge projection
    float usel = t4 ? uab : (t5 ? ubc : uca);
    V3 vsel = sel3(t4, v0, sel3(t5, v1, v2));
    V3 esel = sel3(t4, e10, sel3(t5, e21, e02));
    V3 p;
    p.x = faddr(vsel.x, fmulr(esel.x, usel));
    p.y = faddr(vsel.y, fmulr(esel.y, usel));
    p.z = faddr(vsel.z, fmulr(esel.z, usel));
    V3 w = sub3(Q, p);
    float dB = __fsqrt_rn(dot3(w, w));              // == ref d4/d5/d6 when selected
    float selB = (t4 || t5 || t6) ? dB : 0.0f;

    // merged: at most one term per group; selA+selB reproduces the
    // left-associated reference sum exactly (adding exact zeros).
    return faddr(selA, selB);
}

__global__ __launch_bounds__(64, 16)
void dist_kernel(const float* __restrict__ query,
                 const int* __restrict__ cand,
                 float* __restrict__ out, int N) {
    int i = blockIdx.x * blockDim.x + threadIdx.x;
    if (i >= N) return;

    V3 Q;
    Q.x = __ldg(query + 3 * i + 0);
    Q.y = __ldg(query + 3 * i + 1);
    Q.z = __ldg(query + 3 * i + 2);

    float bestAbs = __int_as_float(0x7f800000);  // +inf
    float bestVal = 0.0f;
    int   bestId  = 0;

    // Candidate row: 10 ints, base 40B-aligned -> 5 x int2 loads.
    const int2* crow2 = (const int2*)(cand + (long long)i * CAND);

    // Prefetch pipeline on candidate ids: next pair's ids are loaded before
    // the current pair's compute, so the id-load latency overlaps math.
    int2 cc = __ldg(crow2 + 0);

#pragma unroll 1
    for (int p = 0; p < CAND / 2; p++) {
        int fa = cc.x, fb = cc.y;

        // Issue all 6 gathers up front: MLP=6 on the L1 critical path.
        float4 A0 = __ldg(&g_fv[3 * fa + 0]);
        float4 B0 = __ldg(&g_fv[3 * fa + 1]);
        float4 C0 = __ldg(&g_fv[3 * fa + 2]);
        float4 A1 = __ldg(&g_fv[3 * fb + 0]);
        float4 B1 = __ldg(&g_fv[3 * fb + 1]);
        float4 C1 = __ldg(&g_fv[3 * fb + 2]);

        // Prefetch next iteration's ids while the 6 gathers are in flight.
        if (p + 1 < CAND / 2) cc = __ldg(crow2 + p + 1);

        float m0 = cand_merged(Q, A0, B0, C0);
        float am0 = fabsf(m0);
        if (am0 < bestAbs) {   // strict < -> first minimum, matches jnp.argmin
            bestAbs = am0; bestVal = m0; bestId = fa;
        }

        float m1 = cand_merged(Q, A1, B1, C1);
        float am1 = fabsf(m1);
        if (am1 < bestAbs) {
            bestAbs = am1; bestVal = m1; bestId = fb;
        }
    }

    out[i]     = (float)bestId;  // ret  (ids < 2^24, exact in f32)
    out[N + i] = bestVal;        // md
}

extern "C" void kernel_launch(void* const* d_in, const int* in_sizes, int n_in,
                              void* d_out, int out_size) {
    const float* query = (const float*)d_in[0];   // (N,3) f32
    const float* verts = (const float*)d_in[1];   // (V,3) f32
    const int*   faces = (const int*)d_in[2];     // (F,3) i32
    const int*   cand  = (const int*)d_in[3];     // (N,C) i32

    int N = in_sizes[3] / CAND;
    int F = in_sizes[2] / 3;

    pack_faces_kernel<<<(F + 255) / 256, 256>>>(verts, faces, F);
    dist_kernel<<<(N + 63) / 64, 64>>>(query, cand, (float*)d_out, N);
}

// round 16
// speedup vs baseline: 1.5708x; 1.5708x over previous
#include <cuda_runtime.h>
#include <cstdint>

// Problem constants (shape-fixed dataset): N=500000, C=10, V=100000, F=200000
#define MAXF 200000
#define CAND 10

// Packed per-face record (48B): [v0|un.x] [v1|un.y] [v2|un.z]
// un = fN / max(||fN||, 1e-9) precomputed with reference-identical ops.
__device__ float4 g_fv[3 * MAXF];

// ---- exact IEEE fp32 helpers (no FMA contraction, match XLA rounding) ----
__device__ __forceinline__ float fmulr(float a, float b) { return __fmul_rn(a, b); }
__device__ __forceinline__ float faddr(float a, float b) { return __fadd_rn(a, b); }
__device__ __forceinline__ float fsubr(float a, float b) { return __fsub_rn(a, b); }

struct V3 { float x, y, z; };

__device__ __forceinline__ V3 sub3(V3 a, V3 b) {
    V3 r; r.x = fsubr(a.x, b.x); r.y = fsubr(a.y, b.y); r.z = fsubr(a.z, b.z); return r;
}
// sum(a*b) left-associated: ((x+y)+z), matching jnp.sum over axis -1
__device__ __forceinline__ float dot3(V3 a, V3 b) {
    return faddr(faddr(fmulr(a.x, b.x), fmulr(a.y, b.y)), fmulr(a.z, b.z));
}
// jnp.cross: (ay*bz - az*by, az*bx - ax*bz, ax*by - ay*bx)
__device__ __forceinline__ V3 cross3(V3 a, V3 b) {
    V3 r;
    r.x = fsubr(fmulr(a.y, b.z), fmulr(a.z, b.y));
    r.y = fsubr(fmulr(a.z, b.x), fmulr(a.x, b.z));
    r.z = fsubr(fmulr(a.x, b.y), fmulr(a.y, b.x));
    return r;
}
__device__ __forceinline__ V3 sel3(bool p, V3 a, V3 b) {
    V3 r; r.x = p ? a.x : b.x; r.y = p ? a.y : b.y; r.z = p ? a.z : b.z; return r;
}

__global__ void pack_faces_kernel(const float* __restrict__ verts,
                                  const int* __restrict__ faces, int F) {
    int f = blockIdx.x * blockDim.x + threadIdx.x;
    if (f >= F) return;
    int i0 = __ldg(faces + 3 * f + 0);
    int i1 = __ldg(faces + 3 * f + 1);
    int i2 = __ldg(faces + 3 * f + 2);
    V3 v0; v0.x = __ldg(verts + 3 * i0); v0.y = __ldg(verts + 3 * i0 + 1); v0.z = __ldg(verts + 3 * i0 + 2);
    V3 v1; v1.x = __ldg(verts + 3 * i1); v1.y = __ldg(verts + 3 * i1 + 1); v1.z = __ldg(verts + 3 * i1 + 2);
    V3 v2; v2.x = __ldg(verts + 3 * i2); v2.y = __ldg(verts + 3 * i2 + 1); v2.z = __ldg(verts + 3 * i2 + 2);

    // Reference-identical unit normal computation
    V3 e10 = sub3(v1, v0);
    V3 e02 = sub3(v0, v2);
    V3 cr  = cross3(e10, e02);
    V3 fN; fN.x = -cr.x; fN.y = -cr.y; fN.z = -cr.z;
    float nn  = dot3(fN, fN);
    float nrm = __fsqrt_rn(nn);
    float den = fmaxf(nrm, 1e-9f);
    float unx = __fdiv_rn(fN.x, den);
    float uny = __fdiv_rn(fN.y, den);
    float unz = __fdiv_rn(fN.z, den);

    g_fv[3 * f + 0] = make_float4(v0.x, v0.y, v0.z, unx);
    g_fv[3 * f + 1] = make_float4(v1.x, v1.y, v1.z, uny);
    g_fv[3 * f + 2] = make_float4(v2.x, v2.y, v2.z, unz);
}

// Compute merged distance for one candidate from its already-loaded record.
__device__ __forceinline__ float cand_merged(
    V3 Q, float4 A, float4 B, float4 Cc)
{
    V3 v0; v0.x = A.x;  v0.y = A.y;  v0.z = A.z;
    V3 v1; v1.x = B.x;  v1.y = B.y;  v1.z = B.z;
    V3 v2; v2.x = Cc.x; v2.y = Cc.y; v2.z = Cc.z;
    V3 un; un.x = A.w;  un.y = B.w;  un.z = Cc.w;

    V3 e10 = sub3(v1, v0);
    V3 e21 = sub3(v2, v1);
    V3 e02 = sub3(v0, v2);

    V3 qm0 = sub3(Q, v0);
    V3 qm1 = sub3(Q, v1);
    V3 qm2 = sub3(Q, v2);

    float uab = __fdiv_rn(dot3(qm0, e10), fmaxf(dot3(e10, e10), 1e-9f));
    float ubc = __fdiv_rn(dot3(qm1, e21), fmaxf(dot3(e21, e21), 1e-9f));
    float uca = __fdiv_rn(dot3(qm2, e02), fmaxf(dot3(e02, e02), 1e-9f));

    bool t1 = (uca > 1.0f) && (uab < 0.0f);
    bool t2 = (uab > 1.0f) && (ubc < 0.0f);
    bool t3 = (ubc > 1.0f) && (uca < 0.0f);

    // fN = -cross(e10, e02) (needed only for the not-above tests)
    V3 cr = cross3(e10, e02);
    V3 fN; fN.x = -cr.x; fN.y = -cr.y; fN.z = -cr.z;
    bool na4 = dot3(cross3(fN, e10), qm0) <= 0.0f;
    bool na5 = dot3(cross3(fN, e21), qm1) <= 0.0f;
    bool na6 = dot3(cross3(fN, e02), qm2) <= 0.0f;

    bool t4 = (uab >= 0.0f) && (uab <= 1.0f) && na4;
    bool t5 = (ubc >= 0.0f) && (ubc <= 1.0f) && na5 && !t4;
    bool t6 = (uca >= 0.0f) && (uca <= 1.0f) && na6 && !t4 && !t5;
    bool t0 = !(t1 || t2 || t3 || t4 || t5 || t6);

    // Group A term: t0->d0, t1->|q-v0|, t2->|q-v1|, t3->|q-v2|  (mutually exclusive)
    float d0 = dot3(qm0, un);                       // un precomputed, bit-identical
    V3 qsel = sel3(t1, qm0, sel3(t2, qm1, qm2));    // t3 (or unused) -> qm2
    float dA = __fsqrt_rn(dot3(qsel, qsel));        // == ref d1/d2/d3 when selected
    float selA = t0 ? d0 : ((t1 || t2 || t3) ? dA : 0.0f);

    // Group B term: t4/t5/t6 (mutually exclusive) -> dist to edge projection
    float usel = t4 ? uab : (t5 ? ubc : uca);
    V3 vsel = sel3(t4, v0, sel3(t5, v1, v2));
    V3 esel = sel3(t4, e10, sel3(t5, e21, e02));
    V3 p;
    p.x = faddr(vsel.x, fmulr(esel.x, usel));
    p.y = faddr(vsel.y, fmulr(esel.y, usel));
    p.z = faddr(vsel.z, fmulr(esel.z, usel));
    V3 w = sub3(Q, p);
    float dB = __fsqrt_rn(dot3(w, w));              // == ref d4/d5/d6 when selected
    float selB = (t4 || t5 || t6) ? dB : 0.0f;

    // merged: at most one term per group; selA+selB reproduces the
    // left-associated reference sum exactly (adding exact zeros).
    return faddr(selA, selB);
}

__global__ __launch_bounds__(64)
void dist_kernel(const float* __restrict__ query,
                 const int* __restrict__ cand,
                 float* __restrict__ out, int N) {
    int i = blockIdx.x * blockDim.x + threadIdx.x;
    if (i >= N) return;

    V3 Q;
    Q.x = __ldg(query + 3 * i + 0);
    Q.y = __ldg(query + 3 * i + 1);
    Q.z = __ldg(query + 3 * i + 2);

    float bestAbs = __int_as_float(0x7f800000);  // +inf
    float bestVal = 0.0f;
    int   bestId  = 0;

    // Candidate row: 10 ints, base 40B-aligned -> 5 x int2 loads.
    const int2* crow2 = (const int2*)(cand + (long long)i * CAND);

    // Prefetch pipeline on candidate ids: next pair's ids are loaded before
    // the current pair's compute, so the id-load latency overlaps math.
    int2 cc = __ldg(crow2 + 0);

#pragma unroll 1
    for (int p = 0; p < CAND / 2; p++) {
        int fa = cc.x, fb = cc.y;

        // Issue all 6 gathers up front: MLP=6 on the L1 critical path.
        float4 A0 = __ldg(&g_fv[3 * fa + 0]);
        float4 B0 = __ldg(&g_fv[3 * fa + 1]);
        float4 C0 = __ldg(&g_fv[3 * fa + 2]);
        float4 A1 = __ldg(&g_fv[3 * fb + 0]);
        float4 B1 = __ldg(&g_fv[3 * fb + 1]);
        float4 C1 = __ldg(&g_fv[3 * fb + 2]);

        // Prefetch next iteration's ids while the 6 gathers are in flight.
        if (p + 1 < CAND / 2) cc = __ldg(crow2 + p + 1);

        float m0 = cand_merged(Q, A0, B0, C0);
        float am0 = fabsf(m0);
        if (am0 < bestAbs) {   // strict < -> first minimum, matches jnp.argmin
            bestAbs = am0; bestVal = m0; bestId = fa;
        }

        float m1 = cand_merged(Q, A1, B1, C1);
        float am1 = fabsf(m1);
        if (am1 < bestAbs) {
            bestAbs = am1; bestVal = m1; bestId = fb;
        }
    }

    out[i]     = (float)bestId;  // ret  (ids < 2^24, exact in f32)
    out[N + i] = bestVal;        // md
}

extern "C" void kernel_launch(void* const* d_in, const int* in_sizes, int n_in,
                              void* d_out, int out_size) {
    const float* query = (const float*)d_in[0];   // (N,3) f32
    const float* verts = (const float*)d_in[1];   // (V,3) f32
    const int*   faces = (const int*)d_in[2];     // (F,3) i32
    const int*   cand  = (const int*)d_in[3];     // (N,C) i32

    int N = in_sizes[3] / CAND;
    int F = in_sizes[2] / 3;

    pack_faces_kernel<<<(F + 255) / 256, 256>>>(verts, faces, F);
    dist_kernel<<<(N + 63) / 64, 64>>>(query, cand, (float*)d_out, N);
}